// round 1
// baseline (speedup 1.0000x reference)
#include <cuda_runtime.h>
#include <math.h>

// Problem constants (fixed shapes from setup_inputs):
// feat0 [2,256,200,200] f32, feat1 [2,256,100,100], feat2 [2,256,50,50],
// feat3 [2,256,25,25], boxes [2,256,4] f32. Output [512,256,7,7] f32.
#define KROIS   512
#define NC      256
#define LPB     256          // boxes per batch (L); batch = k >> 8
#define OUTHW   7
#define NBINS   49           // 7*7
#define SR      2
#define NS      14           // OUT*SR sample coords per axis

// Per-ROI precomputed interpolation tables (scratch; no allocs allowed).
// int4 = {lo, hi, bitcast(frac), unused}
__device__ int4 g_yinfo[KROIS * NS];
__device__ int4 g_xinfo[KROIS * NS];
__device__ int  g_level[KROIS];

__global__ void roi_setup_kernel(const float* __restrict__ boxes)
{
    int k = blockIdx.x * blockDim.x + threadIdx.x;
    if (k >= KROIS) return;

    float x1 = boxes[k * 4 + 0];
    float y1 = boxes[k * 4 + 1];
    float x2 = boxes[k * 4 + 2];
    float y2 = boxes[k * 4 + 3];

    // FPN level: floor(4 + log2(sqrt(area)/224) + eps), clip [2,5], -2
    float area = (x2 - x1) * (y2 - y1);
    float s    = sqrtf(area);
    float lvl  = floorf(4.0f + log2f(s / 224.0f) + 1e-6f);
    lvl = fminf(fmaxf(lvl, 2.0f), 5.0f);
    int level = (int)lvl - 2;
    g_level[k] = level;

    const float scales[4] = {0.25f, 0.125f, 0.0625f, 0.03125f};
    const int   dims[4]   = {200, 100, 50, 25};
    float sc = scales[level];
    int   H  = dims[level];
    int   W  = dims[level];

    float x1s = x1 * sc, y1s = y1 * sc;
    float x2s = x2 * sc, y2s = y2 * sc;
    float roi_w = fmaxf(x2s - x1s, 1.0f);
    float roi_h = fmaxf(y2s - y1s, 1.0f);
    float bin_w = roi_w / (float)OUTHW;
    float bin_h = roi_h / (float)OUTHW;
    float half_bw = bin_w * 0.5f;   // bin_w / SR
    float half_bh = bin_h * 0.5f;

    #pragma unroll
    for (int si = 0; si < NS; si++) {
        int p = si >> 1;        // output bin index
        int i = si & 1;         // subsample index
        // --- y coordinate ---
        {
            float c = y1s + (float)p * bin_h + ((float)i + 0.5f) * half_bh;
            c = fmaxf(c, 0.0f);
            int lo = (int)c;
            int hi;
            if (lo >= H - 1) { lo = H - 1; hi = H - 1; }
            else             { hi = lo + 1; }
            float l = c - (float)lo;
            g_yinfo[k * NS + si] = make_int4(lo, hi, __float_as_int(l), 0);
        }
        // --- x coordinate ---
        {
            float c = x1s + (float)p * bin_w + ((float)i + 0.5f) * half_bw;
            c = fmaxf(c, 0.0f);
            int lo = (int)c;
            int hi;
            if (lo >= W - 1) { lo = W - 1; hi = W - 1; }
            else             { hi = lo + 1; }
            float l = c - (float)lo;
            g_xinfo[k * NS + si] = make_int4(lo, hi, __float_as_int(l), 0);
        }
    }
}

__global__ void __launch_bounds__(256)
roi_align_kernel(const float* __restrict__ f0,
                 const float* __restrict__ f1,
                 const float* __restrict__ f2,
                 const float* __restrict__ f3,
                 float* __restrict__ out)
{
    int idx = blockIdx.x * blockDim.x + threadIdx.x;   // exact grid, no bounds check needed
    // Decompose: idx = ((k*NC + c)*7 + ph)*7 + pw  (matches output layout → coalesced stores)
    int k   = idx / (NC * NBINS);
    int r   = idx - k * (NC * NBINS);
    int c   = r / NBINS;
    int bin = r - c * NBINS;
    int ph  = bin / OUTHW;
    int pw  = bin - ph * OUTHW;

    int level = g_level[k];   // uniform within warp (warp spans <=2 channels of one ROI)
    const float* feat;
    int HW;
    switch (level) {
        case 0:  feat = f0; HW = 200; break;
        case 1:  feat = f1; HW = 100; break;
        case 2:  feat = f2; HW = 50;  break;
        default: feat = f3; HW = 25;  break;
    }
    int b = k >> 8;   // k / LPB
    const float* __restrict__ base = feat + ((size_t)(b * NC + c)) * (size_t)(HW * HW);

    int4 ya = g_yinfo[k * NS + ph * 2 + 0];
    int4 yb = g_yinfo[k * NS + ph * 2 + 1];
    int4 xa = g_xinfo[k * NS + pw * 2 + 0];
    int4 xb = g_xinfo[k * NS + pw * 2 + 1];

    float acc = 0.0f;
    #pragma unroll
    for (int iy = 0; iy < 2; iy++) {
        int4 Y = iy ? yb : ya;
        float ly = __int_as_float(Y.z);
        float hy = 1.0f - ly;
        const float* rlo = base + Y.x * HW;
        const float* rhi = base + Y.y * HW;
        #pragma unroll
        for (int ix = 0; ix < 2; ix++) {
            int4 X = ix ? xb : xa;
            float lx = __int_as_float(X.z);
            float hx = 1.0f - lx;
            float v00 = __ldg(rlo + X.x);
            float v01 = __ldg(rlo + X.y);
            float v10 = __ldg(rhi + X.x);
            float v11 = __ldg(rhi + X.y);
            acc += hy * hx * v00 + hy * lx * v01 + ly * hx * v10 + ly * lx * v11;
        }
    }
    out[idx] = acc * 0.25f;
}

extern "C" void kernel_launch(void* const* d_in, const int* in_sizes, int n_in,
                              void* d_out, int out_size)
{
    const float* f0    = (const float*)d_in[0];
    const float* f1    = (const float*)d_in[1];
    const float* f2    = (const float*)d_in[2];
    const float* f3    = (const float*)d_in[3];
    const float* boxes = (const float*)d_in[4];
    float* out = (float*)d_out;

    roi_setup_kernel<<<1, KROIS>>>(boxes);

    const int total  = KROIS * NC * NBINS;        // 6,422,528
    const int tpb    = 256;
    const int blocks = total / tpb;               // 25088, exact
    roi_align_kernel<<<blocks, tpb>>>(f0, f1, f2, f3, out);
}